// round 12
// baseline (speedup 1.0000x reference)
#include <cuda_runtime.h>
#include <cuda_bf16.h>
#include <cuda_fp16.h>
#include <math.h>
#include <cstdint>

// Shapes
#define BATCH 64
#define TT    50
#define VOC   32000
#define EDIM  64
#define DH    128
#define NH    8
#define MDIM  256
#define NTOK  (BATCH*TT)      // 3200
#define HD    (NH*DH)         // 1024

// ---------------------------------------------------------------------------
// Scratch (no allocations allowed -> __device__ globals)
// ---------------------------------------------------------------------------
__device__ float g_h[NTOK*EDIM];
__device__ float g_Q[NTOK*HD];
__device__ float g_K[NTOK*HD];
__device__ float g_V[NTOK*HD];
__device__ float g_O[NTOK*HD];
__device__ float g_a[NTOK*EDIM];
__device__ float g_m[NTOK*MDIM];
__device__ float g_y[NTOK*EDIM];
__device__ float g_part[8*NTOK*EDIM];          // K-split partials
// Int8 2-digit operands for the final vocab GEMM.
// y row r quantized: a = round(y/sA) (|a|<=32512), a = a1*256 + a0 (both int8).
// Row layout: [a1 digits (64B) | a0 digits (64B)] = 8 uint4.
// Wf col n likewise: [b1 (64B) | b0 (64B)].
// y.w = sA*sB*(65536*S11 + 256*(S10+S01)) + dropped S00 (~2^-16 rel).
__device__ uint4 g_yq[NTOK*8];
__device__ uint4 g_Wfq[VOC*8];
__device__ float g_ysc[NTOK];
__device__ float g_wsc[VOC];

// ---------------------------------------------------------------------------
// f32x2 packed math (FFMA2)
// ---------------------------------------------------------------------------
__device__ __forceinline__ unsigned long long pack2(float x, float y) {
    unsigned long long r;
    asm("mov.b64 %0, {%1, %2};" : "=l"(r) : "f"(x), "f"(y));
    return r;
}
__device__ __forceinline__ float2 unpack2(unsigned long long v) {
    float2 r;
    asm("mov.b64 {%0, %1}, %2;" : "=f"(r.x), "=f"(r.y) : "l"(v));
    return r;
}
__device__ __forceinline__ void ffma2(unsigned long long& d,
                                      unsigned long long a,
                                      unsigned long long b) {
    asm("fma.rn.f32x2 %0, %1, %2, %0;" : "+l"(d) : "l"(a), "l"(b));
}

__device__ __forceinline__ float act_apply(float v, int act) {
    if (act == 1) {
        v = 0.5f * v * (1.0f + erff(v * 0.70710678118654752f));
    }
    return v;
}

// ---------------------------------------------------------------------------
// Warp IMMA s8 (compute_80+; compiles at compute_103)
// ---------------------------------------------------------------------------
__device__ __forceinline__ void imma16832(int* d, const uint32_t* a, const uint32_t* b) {
    asm volatile("mma.sync.aligned.m16n8k32.row.col.s32.s8.s8.s32 "
        "{%0,%1,%2,%3}, {%4,%5,%6,%7}, {%8,%9}, {%0,%1,%2,%3};"
        : "+r"(d[0]), "+r"(d[1]), "+r"(d[2]), "+r"(d[3])
        : "r"(a[0]), "r"(a[1]), "r"(a[2]), "r"(a[3]), "r"(b[0]), "r"(b[1]));
}

// ---------------------------------------------------------------------------
// fp32x2 tile GEMM core: 64x64 tile, optional bias (nullptr -> 0), act.
// ---------------------------------------------------------------------------
__device__ void gemm64_core(const float* __restrict__ A, int lda,
                            const float* __restrict__ B, int ldb,
                            const float* __restrict__ bias,
                            float* __restrict__ C, int ldc,
                            int K, int act) {
    __shared__ float As[64][68];
    __shared__ float Bs[64][64];

    const int tid = threadIdx.x;
    const int tn  = (tid & 15) * 4;
    const int tm  = (tid >> 4) * 4;

    unsigned long long acc[4][2];
#pragma unroll
    for (int i = 0; i < 4; i++) { acc[i][0] = 0ull; acc[i][1] = 0ull; }

    for (int k0 = 0; k0 < K; k0 += 64) {
#pragma unroll
        for (int i = 0; i < 4; i++) {
            int idx = i * 256 + tid;
            int r = idx >> 4;
            int c = (idx & 15) * 4;
            float4 v = *(const float4*)(A + (long long)r * lda + k0 + c);
            *(float4*)&As[r][c] = v;
        }
#pragma unroll
        for (int i = 0; i < 4; i++) {
            int idx = i * 256 + tid;
            int r = idx >> 4;
            int c = (idx & 15) * 4;
            float4 v = *(const float4*)(B + (long long)(k0 + r) * ldb + c);
            *(float4*)&Bs[r][c] = v;
        }
        __syncthreads();

#pragma unroll 8
        for (int k = 0; k < 64; k++) {
            float a0 = As[tm + 0][k];
            float a1 = As[tm + 1][k];
            float a2 = As[tm + 2][k];
            float a3 = As[tm + 3][k];
            float4 b4 = *(const float4*)&Bs[k][tn];
            unsigned long long b01 = pack2(b4.x, b4.y);
            unsigned long long b23 = pack2(b4.z, b4.w);
            unsigned long long aa;
            aa = pack2(a0, a0); ffma2(acc[0][0], aa, b01); ffma2(acc[0][1], aa, b23);
            aa = pack2(a1, a1); ffma2(acc[1][0], aa, b01); ffma2(acc[1][1], aa, b23);
            aa = pack2(a2, a2); ffma2(acc[2][0], aa, b01); ffma2(acc[2][1], aa, b23);
            aa = pack2(a3, a3); ffma2(acc[3][0], aa, b01); ffma2(acc[3][1], aa, b23);
        }
        __syncthreads();
    }

    float4 bv4 = make_float4(0.f, 0.f, 0.f, 0.f);
    if (bias) bv4 = *(const float4*)(bias + tn);
#pragma unroll
    for (int i = 0; i < 4; i++) {
        float2 p0 = unpack2(acc[i][0]);
        float2 p1 = unpack2(acc[i][1]);
        float4 o;
        o.x = act_apply(p0.x + bv4.x, act);
        o.y = act_apply(p0.y + bv4.y, act);
        o.z = act_apply(p1.x + bv4.z, act);
        o.w = act_apply(p1.y + bv4.w, act);
        *(float4*)(C + (long long)(tm + i) * ldc + tn) = o;
    }
}

// ---------------------------------------------------------------------------
// Kernels
// ---------------------------------------------------------------------------
__global__ void embed_kernel(const int* __restrict__ x,
                             const float* __restrict__ tok,
                             const float* __restrict__ pos) {
    int i = blockIdx.x * 256 + threadIdx.x;
    if (i >= NTOK * EDIM) return;
    int m = i >> 6;
    int e = i & 63;
    int t = m % TT;
    int id = x[m];
    g_h[i] = tok[id * EDIM + e] + pos[t * EDIM + e];
}

__global__ void qkv_kernel(const float* __restrict__ Wq, const float* __restrict__ bq,
                           const float* __restrict__ Wk, const float* __restrict__ bk,
                           const float* __restrict__ Wv, const float* __restrict__ bv) {
    int m0   = blockIdx.x * 64;
    int head = blockIdx.y >> 1;
    int dt   = blockIdx.y & 1;
    const float* W; const float* bb; float* C;
    if (blockIdx.z == 0)      { W = Wq; bb = bq; C = g_Q; }
    else if (blockIdx.z == 1) { W = Wk; bb = bk; C = g_K; }
    else                      { W = Wv; bb = bv; C = g_V; }
    int n0 = head * DH + dt * 64;
    gemm64_core(g_h + (long long)m0 * EDIM, EDIM,
                W + head * EDIM * DH + dt * 64, DH,
                bb + n0,
                C + (long long)m0 * HD + n0, HD,
                EDIM, 0);
}

// ---------------------------------------------------------------------------
// Attention: one block per (b,h). Register-tiled micro-GEMMs.
// ---------------------------------------------------------------------------
#define AT_QT 0
#define AT_KT 8192
#define AT_V  16384
#define AT_S  22784
#define AT_SMEM (27136 * 4)

__global__ __launch_bounds__(256) void attn_kernel() {
    extern __shared__ float sm[];
    float* sQT = sm + AT_QT;
    float* sKT = sm + AT_KT;
    float* sV  = sm + AT_V;
    float* sS  = sm + AT_S;

    int bh = blockIdx.x;
    int b = bh >> 3, h = bh & 7;
    int tid = threadIdx.x;
    int wid = tid >> 5, lane = tid & 31;

    const float* Qb = g_Q + (long long)(b * TT) * HD + h * DH;
    const float* Kb = g_K + (long long)(b * TT) * HD + h * DH;
    const float* Vb = g_V + (long long)(b * TT) * HD + h * DH;

    for (int i = tid; i < 2048; i += 256) {      // 32 d4-groups x 64 t
        int d4 = i >> 6, t = i & 63;
        float4 q = make_float4(0.f, 0.f, 0.f, 0.f);
        float4 k = make_float4(0.f, 0.f, 0.f, 0.f);
        if (t < TT) {
            q = *(const float4*)(Qb + (long long)t * HD + d4 * 4);
            k = *(const float4*)(Kb + (long long)t * HD + d4 * 4);
        }
        int r = d4 * 4;
        sQT[(r + 0) * 64 + t] = q.x;
        sQT[(r + 1) * 64 + t] = q.y;
        sQT[(r + 2) * 64 + t] = q.z;
        sQT[(r + 3) * 64 + t] = q.w;
        sKT[(r + 0) * 64 + t] = k.x;
        sKT[(r + 1) * 64 + t] = k.y;
        sKT[(r + 2) * 64 + t] = k.z;
        sKT[(r + 3) * 64 + t] = k.w;
    }
    for (int i = tid; i < TT * 32; i += 256) {
        int s = i >> 5, c = i & 31;
        *(float4*)&sV[s * 128 + c * 4] = *(const float4*)(Vb + (long long)s * HD + c * 4);
    }
    __syncthreads();

    // Phase A: scores
    {
        const int tn = (tid & 15) * 4;   // s
        const int tm = (tid >> 4) * 4;   // t
        unsigned long long acc[4][2];
#pragma unroll
        for (int i = 0; i < 4; i++) { acc[i][0] = 0ull; acc[i][1] = 0ull; }

#pragma unroll 8
        for (int k = 0; k < 128; k++) {
            float4 q4 = *(const float4*)&sQT[k * 64 + tm];
            float4 k4 = *(const float4*)&sKT[k * 64 + tn];
            unsigned long long b01 = pack2(k4.x, k4.y);
            unsigned long long b23 = pack2(k4.z, k4.w);
            unsigned long long aa;
            aa = pack2(q4.x, q4.x); ffma2(acc[0][0], aa, b01); ffma2(acc[0][1], aa, b23);
            aa = pack2(q4.y, q4.y); ffma2(acc[1][0], aa, b01); ffma2(acc[1][1], aa, b23);
            aa = pack2(q4.z, q4.z); ffma2(acc[2][0], aa, b01); ffma2(acc[2][1], aa, b23);
            aa = pack2(q4.w, q4.w); ffma2(acc[3][0], aa, b01); ffma2(acc[3][1], aa, b23);
        }
        const float scale = 0.08838834764831845f;  // 1/sqrt(128)
#pragma unroll
        for (int i = 0; i < 4; i++) {
            float2 p0 = unpack2(acc[i][0]);
            float2 p1 = unpack2(acc[i][1]);
            float4 o = make_float4(p0.x * scale, p0.y * scale, p1.x * scale, p1.y * scale);
            *(float4*)&sS[(tm + i) * 68 + tn] = o;
        }
    }
    __syncthreads();

    // Softmax: warp-parallel per row (causal). Warp w handles rows w, w+8, ...
    for (int t = wid; t < TT; t += 8) {
        float* row = sS + t * 68;
        float e0 = -1e30f, e1 = -1e30f;
        bool v0 = (lane < 25) && (2 * lane <= t);
        bool v1 = (lane < 25) && (2 * lane + 1 <= t);
        float2 v = make_float2(0.f, 0.f);
        if (lane < 25) v = *(float2*)(row + 2 * lane);
        if (v0) e0 = v.x;
        if (v1) e1 = v.y;
        float mx = fmaxf(e0, e1);
#pragma unroll
        for (int o = 16; o; o >>= 1) mx = fmaxf(mx, __shfl_xor_sync(0xFFFFFFFFu, mx, o));
        float x0 = v0 ? expf(e0 - mx) : 0.f;
        float x1 = v1 ? expf(e1 - mx) : 0.f;
        float sum = x0 + x1;
#pragma unroll
        for (int o = 16; o; o >>= 1) sum += __shfl_xor_sync(0xFFFFFFFFu, sum, o);
        float inv = 1.0f / sum;
        if (lane < 25) *(float2*)(row + 2 * lane) = make_float2(x0 * inv, x1 * inv);
    }
    __syncthreads();

    // Phase B: O = P*V
    {
        const int tm = (tid >> 5) * 8;   // t
        const int tn = (tid & 31) * 4;   // d
        unsigned long long acc[8][2];
#pragma unroll
        for (int i = 0; i < 8; i++) { acc[i][0] = 0ull; acc[i][1] = 0ull; }

#pragma unroll 2
        for (int s = 0; s < TT; s++) {
            float4 v4 = *(const float4*)&sV[s * 128 + tn];
            unsigned long long b01 = pack2(v4.x, v4.y);
            unsigned long long b23 = pack2(v4.z, v4.w);
#pragma unroll
            for (int i = 0; i < 8; i++) {
                float p = sS[(tm + i) * 68 + s];
                unsigned long long aa = pack2(p, p);
                ffma2(acc[i][0], aa, b01);
                ffma2(acc[i][1], aa, b23);
            }
        }

        float* Ob = g_O + (long long)(b * TT) * HD + h * DH;
#pragma unroll
        for (int i = 0; i < 8; i++) {
            int t = tm + i;
            if (t < TT) {
                float2 p0 = unpack2(acc[i][0]);
                float2 p1 = unpack2(acc[i][1]);
                float4 o = make_float4(p0.x, p0.y, p1.x, p1.y);
                *(float4*)(Ob + (long long)t * HD + tn) = o;
            }
        }
    }
}

// a-partials: K split 8x128.   grid (50, 8)
__global__ void proj_o_part_kernel(const float* __restrict__ Wo) {
    int m0 = blockIdx.x * 64;
    int ks = blockIdx.y;
    gemm64_core(g_O + (long long)m0 * HD + ks * 128, HD,
                Wo + (long long)ks * 128 * EDIM, EDIM, nullptr,
                g_part + (long long)ks * NTOK * EDIM + (long long)m0 * EDIM, EDIM,
                128, 0);
}
// y-partials: K split 4x64.    grid (50, 4)
__global__ void mlp2_part_kernel(const float* __restrict__ W2) {
    int m0 = blockIdx.x * 64;
    int ks = blockIdx.y;
    gemm64_core(g_m + (long long)m0 * MDIM + ks * 64, MDIM,
                W2 + (long long)ks * 64 * EDIM, EDIM, nullptr,
                g_part + (long long)ks * NTOK * EDIM + (long long)m0 * EDIM, EDIM,
                64, 0);
}
// Deterministic partial reduce + bias. DST selects the destination global in
// device code (never pass a __device__ symbol as a kernel arg from host).
template <int NSPLIT, int DST>   // DST: 0 -> g_a, 1 -> g_y
__global__ void reduce_part_kernel(const float* __restrict__ bias) {
    float* dst = (DST == 0) ? g_a : g_y;
    int i = blockIdx.x * 256 + threadIdx.x;
    if (i >= NTOK * EDIM) return;
    float s = bias[i & 63];
#pragma unroll
    for (int k = 0; k < NSPLIT; k++) s += g_part[(long long)k * NTOK * EDIM + i];
    dst[i] = s;
}

// m = gelu(a @ W1 + b1)       grid (50, 4)
__global__ void mlp1_kernel(const float* __restrict__ W1, const float* __restrict__ b1) {
    int m0 = blockIdx.x * 64;
    int n0 = blockIdx.y * 64;
    gemm64_core(g_a + (long long)m0 * EDIM, EDIM, W1 + n0, MDIM, b1 + n0,
                g_m + (long long)m0 * MDIM + n0, MDIM, EDIM, 1);
}

// ---------------------------------------------------------------------------
// Int8 2-digit quantization for the final vocab GEMM.
// a = round(v/s) with |a| <= 32512, s = amax/32512; a1 = (a+128)>>8 (int8),
// a0 = a - a1*256 (int8 in [-128,127]).
// ---------------------------------------------------------------------------
__device__ __forceinline__ void digits16(float v, float inv, int& d1, int& d0) {
    int a = __float2int_rn(v * inv);
    d1 = (a + 128) >> 8;
    d0 = a - (d1 << 8);
}

// Quantize y rows: one warp per row. grid 400 x 256.
__global__ void quant_y_kernel() {
    int r = blockIdx.x * 8 + (threadIdx.x >> 5);
    int lane = threadIdx.x & 31;
    float2 v = *(const float2*)(g_y + r * 64 + lane * 2);
    float am = fmaxf(fabsf(v.x), fabsf(v.y));
#pragma unroll
    for (int o = 16; o; o >>= 1) am = fmaxf(am, __shfl_xor_sync(0xFFFFFFFFu, am, o));
    float s = am > 0.f ? am / 32512.f : 1.f;
    float inv = 32512.f / fmaxf(am, 1e-30f);
    int h0, l0, h1, l1;
    digits16(v.x, inv, h0, l0);
    digits16(v.y, inv, h1, l1);
    unsigned short hi = (unsigned short)((h0 & 0xFF) | ((h1 & 0xFF) << 8));
    unsigned short lo = (unsigned short)((l0 & 0xFF) | ((l1 & 0xFF) << 8));
    ((unsigned short*)g_yq)[r * 64 + lane]      = hi;   // bytes [2lane, 2lane+1]
    ((unsigned short*)g_yq)[r * 64 + 32 + lane] = lo;   // bytes [64+2lane, ...]
    if (lane == 0) g_ysc[r] = s;
}

// Quantize Wf columns. Wf is [E][V]; block handles 128 columns via smem tile.
__global__ void quant_wf_kernel(const float* __restrict__ Wf) {
    __shared__ float sW[64][129];
    int n0 = blockIdx.x * 128;
    int tid = threadIdx.x;  // 128
    for (int i = tid; i < 64 * 128; i += 128) {
        int e = i >> 7, n = i & 127;
        sW[e][n] = Wf[(long long)e * VOC + n0 + n];
    }
    __syncthreads();
    // thread t owns column t
    float am = 0.f;
#pragma unroll 8
    for (int e = 0; e < 64; e++) am = fmaxf(am, fabsf(sW[e][tid]));
    float s = am > 0.f ? am / 32512.f : 1.f;
    float inv = 32512.f / fmaxf(am, 1e-30f);
    unsigned int hw[16], lw[16];
#pragma unroll
    for (int q = 0; q < 16; q++) { hw[q] = 0u; lw[q] = 0u; }
#pragma unroll 8
    for (int e = 0; e < 64; e++) {
        int d1, d0;
        digits16(sW[e][tid], inv, d1, d0);
        hw[e >> 2] |= (unsigned int)(d1 & 0xFF) << ((e & 3) * 8);
        lw[e >> 2] |= (unsigned int)(d0 & 0xFF) << ((e & 3) * 8);
    }
    uint4* dst = g_Wfq + (long long)(n0 + tid) * 8;
#pragma unroll
    for (int q = 0; q < 4; q++)
        dst[q] = make_uint4(hw[q*4], hw[q*4+1], hw[q*4+2], hw[q*4+3]);
#pragma unroll
    for (int q = 0; q < 4; q++)
        dst[4 + q] = make_uint4(lw[q*4], lw[q*4+1], lw[q*4+2], lw[q*4+3]);
    g_wsc[n0 + tid] = s;
}

// ---------------------------------------------------------------------------
// Final vocab GEMM on mma.sync m16n8k32 s8, direct-lds fragments.
// Block tile 128x128, 8 warps (4m x 2n), warp tile 32x64.
// 3 digit-terms x 2 k32-steps = 6 IMMA k-steps (vs 8 HMMA k16 for fp16).
// Smem: 2 * 128 rows * 144 B pitch = 36864 B + scales/bias, < 48KB default.
// Row pitch 144 B: rows differ by 36 words -> 8 rows x 4 lanes hit 32 banks.
// ---------------------------------------------------------------------------
#define FI_PITCH 144

__global__ __launch_bounds__(256) void final_imma_kernel(
        const float* __restrict__ bf, float* __restrict__ out) {
    __shared__ float sBias[128];
    __shared__ float sSB[128];
    __shared__ float sSA[128];
    __shared__ __align__(16) signed char sA[128 * FI_PITCH];
    __shared__ __align__(16) signed char sB[128 * FI_PITCH];

    const int tid = threadIdx.x;
    const int m0 = blockIdx.x * 128;
    const int n0 = blockIdx.y * 128;

    if (tid < 128) {
        sBias[tid] = bf[n0 + tid];
        sSB[tid]   = g_wsc[n0 + tid];
        sSA[tid]   = g_ysc[m0 + tid];
    }

    const uint4* __restrict__ Ag = g_yq + (long long)m0 * 8;
    const uint4* __restrict__ Bg = g_Wfq + (long long)n0 * 8;
#pragma unroll
    for (int i = 0; i < 4; i++) {
        int idx = i * 256 + tid;          // 0..1023
        int r = idx >> 3, q = idx & 7;
        *(uint4*)(sA + r * FI_PITCH + q * 16) = Ag[(long long)r * 8 + q];
        *(uint4*)(sB + r * FI_PITCH + q * 16) = Bg[(long long)r * 8 + q];
    }
    __syncthreads();

    const int wid  = tid >> 5, lane = tid & 31;
    const int wm   = wid >> 1;            // 0..3  (m strip of 32)
    const int wn   = wid & 1;             // 0..1  (n strip of 64)
    const int l4   = lane >> 2;           // 0..7  groupID
    const int lm   = lane & 3;            // 0..3  threadID_in_group

    int accH[2][8][4];   // S11  (weight 65536)
    int accM[2][8][4];   // S10+S01 (weight 256)
#pragma unroll
    for (int mf = 0; mf < 2; mf++)
#pragma unroll
        for (int nf = 0; nf < 8; nf++)
#pragma unroll
            for (int c = 0; c < 4; c++) { accH[mf][nf][c] = 0; accM[mf][nf][c] = 0; }

    // terms: (kA, kB, which acc): (0,0,H), (0,64,M), (64,0,M)
#pragma unroll
    for (int term = 0; term < 3; term++) {
        const int kA = (term == 2) ? 64 : 0;
        const int kB = (term == 1) ? 64 : 0;
#pragma unroll
        for (int ks = 0; ks < 2; ks++) {
            const int oa = kA + ks * 32;
            const int ob = kB + ks * 32;
            uint32_t a[2][4];
#pragma unroll
            for (int mf = 0; mf < 2; mf++) {
                const signed char* base = sA + (wm * 32 + mf * 16 + l4) * FI_PITCH + oa + lm * 4;
                a[mf][0] = *(const uint32_t*)(base);
                a[mf][1] = *(const uint32_t*)(base + 8 * FI_PITCH);
                a[mf][2] = *(const uint32_t*)(base + 16);
                a[mf][3] = *(const uint32_t*)(base + 8 * FI_PITCH + 16);
            }
            uint32_t b[8][2];
#pragma unroll
            for (int nf = 0; nf < 8; nf++) {
                const signed char* base = sB + (wn * 64 + nf * 8 + l4) * FI_PITCH + ob + lm * 4;
                b[nf][0] = *(const uint32_t*)(base);
                b[nf][1] = *(const uint32_t*)(base + 16);
            }
            if (term == 0) {
#pragma unroll
                for (int mf = 0; mf < 2; mf++)
#pragma unroll
                    for (int nf = 0; nf < 8; nf++)
                        imma16832(accH[mf][nf], a[mf], b[nf]);
            } else {
#pragma unroll
                for (int mf = 0; mf < 2; mf++)
#pragma unroll
                    for (int nf = 0; nf < 8; nf++)
                        imma16832(accM[mf][nf], a[mf], b[nf]);
            }
        }
    }

    // Epilogue: r = sA*sB*(65536*H + 256*M) + bias
#pragma unroll
    for (int mf = 0; mf < 2; mf++) {
        int rrel = wm * 32 + mf * 16 + l4;
        int row = m0 + rrel;
        float sa0 = sSA[rrel], sa1 = sSA[rrel + 8];
        float* o0 = out + (long long)row * VOC + n0;
        float* o1 = out + (long long)(row + 8) * VOC + n0;
#pragma unroll
        for (int nf = 0; nf < 8; nf++) {
            int colr = wn * 64 + nf * 8 + lm * 2;
            float sb0 = sSB[colr], sb1 = sSB[colr + 1];
            float bx = sBias[colr], by = sBias[colr + 1];
            const int* H = accH[mf][nf];
            const int* M = accM[mf][nf];
            float2 v0, v1;
            v0.x = sa0 * sb0 * (65536.f * (float)H[0] + 256.f * (float)M[0]) + bx;
            v0.y = sa0 * sb1 * (65536.f * (float)H[1] + 256.f * (float)M[1]) + by;
            v1.x = sa1 * sb0 * (65536.f * (float)H[2] + 256.f * (float)M[2]) + bx;
            v1.y = sa1 * sb1 * (65536.f * (float)H[3] + 256.f * (float)M[3]) + by;
            *(float2*)(o0 + colr) = v0;
            *(float2*)(o1 + colr) = v1;
        }
    }
}

// ---------------------------------------------------------------------------
extern "C" void kernel_launch(void* const* d_in, const int* in_sizes, int n_in,
                              void* d_out, int out_size) {
    (void)in_sizes; (void)n_in; (void)out_size;
    const int*   x   = (const int*)  d_in[0];
    const float* tok = (const float*)d_in[1];
    const float* pos = (const float*)d_in[2];
    const float* Wq  = (const float*)d_in[3];
    const float* bq  = (const float*)d_in[4];
    const float* Wk  = (const float*)d_in[5];
    const float* bk  = (const float*)d_in[6];
    const float* Wv  = (const float*)d_in[7];
    const float* bv  = (const float*)d_in[8];
    const float* Wo  = (const float*)d_in[9];
    const float* bo  = (const float*)d_in[10];
    const float* W1  = (const float*)d_in[11];
    const float* b1  = (const float*)d_in[12];
    const float* W2  = (const float*)d_in[13];
    const float* b2  = (const float*)d_in[14];
    const float* Wf  = (const float*)d_in[15];
    const float* bf  = (const float*)d_in[16];
    float* out = (float*)d_out;

    cudaFuncSetAttribute(attn_kernel, cudaFuncAttributeMaxDynamicSharedMemorySize, AT_SMEM);

    // Wf quantization is independent of everything else — kick it off first.
    quant_wf_kernel<<<VOC / 128, 128>>>(Wf);

    embed_kernel<<<(NTOK * EDIM + 255) / 256, 256>>>(x, tok, pos);
    qkv_kernel<<<dim3(NTOK / 64, 2 * NH, 3), 256>>>(Wq, bq, Wk, bk, Wv, bv);
    attn_kernel<<<BATCH * NH, 256, AT_SMEM>>>();

    proj_o_part_kernel<<<dim3(NTOK / 64, 8), 256>>>(Wo);
    reduce_part_kernel<8, 0><<<(NTOK * EDIM + 255) / 256, 256>>>(bo);

    mlp1_kernel<<<dim3(NTOK / 64, MDIM / 64), 256>>>(W1, b1);

    mlp2_part_kernel<<<dim3(NTOK / 64, 4), 256>>>(W2);
    reduce_part_kernel<4, 1><<<(NTOK * EDIM + 255) / 256, 256>>>(b2);

    quant_y_kernel<<<NTOK / 8, 256>>>();

    final_imma_kernel<<<dim3(NTOK / 128, VOC / 128), 256>>>(bf, out);
}

// round 13
// speedup vs baseline: 1.5633x; 1.5633x over previous
#include <cuda_runtime.h>
#include <cuda_bf16.h>
#include <cuda_fp16.h>
#include <math.h>
#include <cstdint>

// Shapes
#define BATCH 64
#define TT    50
#define VOC   32000
#define EDIM  64
#define DH    128
#define NH    8
#define MDIM  256
#define NTOK  (BATCH*TT)      // 3200
#define HD    (NH*DH)         // 1024

// ---------------------------------------------------------------------------
// Scratch (no allocations allowed -> __device__ globals)
// ---------------------------------------------------------------------------
__device__ float g_Q[NTOK*HD];
__device__ float g_K[NTOK*HD];
__device__ float g_V[NTOK*HD];
__device__ float g_O[NTOK*HD];
__device__ float g_a[NTOK*EDIM];
__device__ float g_m[NTOK*MDIM];
__device__ float g_part[8*NTOK*EDIM];          // K-split partials
// Split-fp16 operands for the final vocab GEMM (fp16: 11-bit mantissa).
// A' row (per token): [hi(64) | lo(64)] fp16  -> 16 uint4
// B' row (per vocab): [hi(64)]          fp16  ->  8 uint4 (reused by both chunks)
// (hiA+loA)*hiB = A*hiB exactly; dropped term A*loB ~2^-12 relative.
__device__ uint4 g_ybf[NTOK*16];
__device__ uint4 g_Wfb[VOC*8];

// ---------------------------------------------------------------------------
// f32x2 packed math (FFMA2)
// ---------------------------------------------------------------------------
__device__ __forceinline__ unsigned long long pack2(float x, float y) {
    unsigned long long r;
    asm("mov.b64 %0, {%1, %2};" : "=l"(r) : "f"(x), "f"(y));
    return r;
}
__device__ __forceinline__ float2 unpack2(unsigned long long v) {
    float2 r;
    asm("mov.b64 {%0, %1}, %2;" : "=f"(r.x), "=f"(r.y) : "l"(v));
    return r;
}
__device__ __forceinline__ void ffma2(unsigned long long& d,
                                      unsigned long long a,
                                      unsigned long long b) {
    asm("fma.rn.f32x2 %0, %1, %2, %0;" : "+l"(d) : "l"(a), "l"(b));
}

__device__ __forceinline__ float act_apply(float v, int act) {
    if (act == 1) {
        v = 0.5f * v * (1.0f + erff(v * 0.70710678118654752f));
    }
    return v;
}

// ---------------------------------------------------------------------------
// Warp MMA fp16 (compute_80+; compiles at compute_103)
// ---------------------------------------------------------------------------
__device__ __forceinline__ void mma16816(float* d, const uint32_t* a, const uint32_t* b) {
    asm volatile("mma.sync.aligned.m16n8k16.row.col.f32.f16.f16.f32 "
        "{%0,%1,%2,%3}, {%4,%5,%6,%7}, {%8,%9}, {%0,%1,%2,%3};"
        : "+f"(d[0]), "+f"(d[1]), "+f"(d[2]), "+f"(d[3])
        : "r"(a[0]), "r"(a[1]), "r"(a[2]), "r"(a[3]), "r"(b[0]), "r"(b[1]));
}

// ---------------------------------------------------------------------------
// fp32x2 tile GEMM core: 64x64 tile, optional bias (nullptr -> 0), act.
// ---------------------------------------------------------------------------
__device__ void gemm64_core(const float* __restrict__ A, int lda,
                            const float* __restrict__ B, int ldb,
                            const float* __restrict__ bias,
                            float* __restrict__ C, int ldc,
                            int K, int act) {
    __shared__ float As[64][68];
    __shared__ float Bs[64][64];

    const int tid = threadIdx.x;
    const int tn  = (tid & 15) * 4;
    const int tm  = (tid >> 4) * 4;

    unsigned long long acc[4][2];
#pragma unroll
    for (int i = 0; i < 4; i++) { acc[i][0] = 0ull; acc[i][1] = 0ull; }

    for (int k0 = 0; k0 < K; k0 += 64) {
#pragma unroll
        for (int i = 0; i < 4; i++) {
            int idx = i * 256 + tid;
            int r = idx >> 4;
            int c = (idx & 15) * 4;
            float4 v = *(const float4*)(A + (long long)r * lda + k0 + c);
            *(float4*)&As[r][c] = v;
        }
#pragma unroll
        for (int i = 0; i < 4; i++) {
            int idx = i * 256 + tid;
            int r = idx >> 4;
            int c = (idx & 15) * 4;
            float4 v = *(const float4*)(B + (long long)(k0 + r) * ldb + c);
            *(float4*)&Bs[r][c] = v;
        }
        __syncthreads();

#pragma unroll 8
        for (int k = 0; k < 64; k++) {
            float a0 = As[tm + 0][k];
            float a1 = As[tm + 1][k];
            float a2 = As[tm + 2][k];
            float a3 = As[tm + 3][k];
            float4 b4 = *(const float4*)&Bs[k][tn];
            unsigned long long b01 = pack2(b4.x, b4.y);
            unsigned long long b23 = pack2(b4.z, b4.w);
            unsigned long long aa;
            aa = pack2(a0, a0); ffma2(acc[0][0], aa, b01); ffma2(acc[0][1], aa, b23);
            aa = pack2(a1, a1); ffma2(acc[1][0], aa, b01); ffma2(acc[1][1], aa, b23);
            aa = pack2(a2, a2); ffma2(acc[2][0], aa, b01); ffma2(acc[2][1], aa, b23);
            aa = pack2(a3, a3); ffma2(acc[3][0], aa, b01); ffma2(acc[3][1], aa, b23);
        }
        __syncthreads();
    }

    float4 bv4 = make_float4(0.f, 0.f, 0.f, 0.f);
    if (bias) bv4 = *(const float4*)(bias + tn);
#pragma unroll
    for (int i = 0; i < 4; i++) {
        float2 p0 = unpack2(acc[i][0]);
        float2 p1 = unpack2(acc[i][1]);
        float4 o;
        o.x = act_apply(p0.x + bv4.x, act);
        o.y = act_apply(p0.y + bv4.y, act);
        o.z = act_apply(p1.x + bv4.z, act);
        o.w = act_apply(p1.y + bv4.w, act);
        *(float4*)(C + (long long)(tm + i) * ldc + tn) = o;
    }
}

// ---------------------------------------------------------------------------
// QKV with fused embedding: A tile (h = tok[x]+pos) is gathered on the fly.
// grid (50, 16, 3): y = head*2 + dtile, z selects Q/K/V.  K=64 single chunk.
// ---------------------------------------------------------------------------
__global__ void qkv_embed_kernel(const int* __restrict__ x,
                                 const float* __restrict__ tok,
                                 const float* __restrict__ pos,
                                 const float* __restrict__ Wq, const float* __restrict__ bq,
                                 const float* __restrict__ Wk, const float* __restrict__ bk,
                                 const float* __restrict__ Wv, const float* __restrict__ bv) {
    __shared__ float As[64][68];
    __shared__ float Bs[64][64];

    const int tid = threadIdx.x;
    int m0   = blockIdx.x * 64;
    int head = blockIdx.y >> 1;
    int dt   = blockIdx.y & 1;
    const float* W; const float* bb; float* C;
    if (blockIdx.z == 0)      { W = Wq; bb = bq; C = g_Q; }
    else if (blockIdx.z == 1) { W = Wk; bb = bk; C = g_K; }
    else                      { W = Wv; bb = bv; C = g_V; }
    int n0 = head * DH + dt * 64;
    const float* B = W + head * EDIM * DH + dt * 64;       // ldb = DH
    const float* bias = bb + n0;
    float* Cp = C + (long long)m0 * HD + n0;               // ldc = HD

    const int tn  = (tid & 15) * 4;
    const int tm  = (tid >> 4) * 4;

    // A tile: h[m0+r][c..c+3] = tok[x]*... gathered
#pragma unroll
    for (int i = 0; i < 4; i++) {
        int idx = i * 256 + tid;
        int r = idx >> 4;
        int c = (idx & 15) * 4;
        int m = m0 + r;
        int id = x[m];
        int t = m % TT;
        float4 tv = *(const float4*)(tok + id * EDIM + c);
        float4 pv = *(const float4*)(pos + t * EDIM + c);
        float4 v = make_float4(tv.x + pv.x, tv.y + pv.y, tv.z + pv.z, tv.w + pv.w);
        *(float4*)&As[r][c] = v;
    }
#pragma unroll
    for (int i = 0; i < 4; i++) {
        int idx = i * 256 + tid;
        int r = idx >> 4;
        int c = (idx & 15) * 4;
        float4 v = *(const float4*)(B + (long long)r * DH + c);
        *(float4*)&Bs[r][c] = v;
    }
    __syncthreads();

    unsigned long long acc[4][2];
#pragma unroll
    for (int i = 0; i < 4; i++) { acc[i][0] = 0ull; acc[i][1] = 0ull; }

#pragma unroll 8
    for (int k = 0; k < 64; k++) {
        float a0 = As[tm + 0][k];
        float a1 = As[tm + 1][k];
        float a2 = As[tm + 2][k];
        float a3 = As[tm + 3][k];
        float4 b4 = *(const float4*)&Bs[k][tn];
        unsigned long long b01 = pack2(b4.x, b4.y);
        unsigned long long b23 = pack2(b4.z, b4.w);
        unsigned long long aa;
        aa = pack2(a0, a0); ffma2(acc[0][0], aa, b01); ffma2(acc[0][1], aa, b23);
        aa = pack2(a1, a1); ffma2(acc[1][0], aa, b01); ffma2(acc[1][1], aa, b23);
        aa = pack2(a2, a2); ffma2(acc[2][0], aa, b01); ffma2(acc[2][1], aa, b23);
        aa = pack2(a3, a3); ffma2(acc[3][0], aa, b01); ffma2(acc[3][1], aa, b23);
    }

    float4 bv4 = *(const float4*)(bias + tn);
#pragma unroll
    for (int i = 0; i < 4; i++) {
        float2 p0 = unpack2(acc[i][0]);
        float2 p1 = unpack2(acc[i][1]);
        float4 o = make_float4(p0.x + bv4.x, p0.y + bv4.y, p1.x + bv4.z, p1.y + bv4.w);
        *(float4*)(Cp + (long long)(tm + i) * HD + tn) = o;
    }
}

// ---------------------------------------------------------------------------
// Attention: one block per (b,h). Register-tiled micro-GEMMs.
// ---------------------------------------------------------------------------
#define AT_QT 0
#define AT_KT 8192
#define AT_V  16384
#define AT_S  22784
#define AT_SMEM (27136 * 4)

__global__ __launch_bounds__(256) void attn_kernel() {
    extern __shared__ float sm[];
    float* sQT = sm + AT_QT;
    float* sKT = sm + AT_KT;
    float* sV  = sm + AT_V;
    float* sS  = sm + AT_S;

    int bh = blockIdx.x;
    int b = bh >> 3, h = bh & 7;
    int tid = threadIdx.x;
    int wid = tid >> 5, lane = tid & 31;

    const float* Qb = g_Q + (long long)(b * TT) * HD + h * DH;
    const float* Kb = g_K + (long long)(b * TT) * HD + h * DH;
    const float* Vb = g_V + (long long)(b * TT) * HD + h * DH;

    for (int i = tid; i < 2048; i += 256) {      // 32 d4-groups x 64 t
        int d4 = i >> 6, t = i & 63;
        float4 q = make_float4(0.f, 0.f, 0.f, 0.f);
        float4 k = make_float4(0.f, 0.f, 0.f, 0.f);
        if (t < TT) {
            q = *(const float4*)(Qb + (long long)t * HD + d4 * 4);
            k = *(const float4*)(Kb + (long long)t * HD + d4 * 4);
        }
        int r = d4 * 4;
        sQT[(r + 0) * 64 + t] = q.x;
        sQT[(r + 1) * 64 + t] = q.y;
        sQT[(r + 2) * 64 + t] = q.z;
        sQT[(r + 3) * 64 + t] = q.w;
        sKT[(r + 0) * 64 + t] = k.x;
        sKT[(r + 1) * 64 + t] = k.y;
        sKT[(r + 2) * 64 + t] = k.z;
        sKT[(r + 3) * 64 + t] = k.w;
    }
    for (int i = tid; i < TT * 32; i += 256) {
        int s = i >> 5, c = i & 31;
        *(float4*)&sV[s * 128 + c * 4] = *(const float4*)(Vb + (long long)s * HD + c * 4);
    }
    __syncthreads();

    // Phase A: scores
    {
        const int tn = (tid & 15) * 4;   // s
        const int tm = (tid >> 4) * 4;   // t
        unsigned long long acc[4][2];
#pragma unroll
        for (int i = 0; i < 4; i++) { acc[i][0] = 0ull; acc[i][1] = 0ull; }

#pragma unroll 8
        for (int k = 0; k < 128; k++) {
            float4 q4 = *(const float4*)&sQT[k * 64 + tm];
            float4 k4 = *(const float4*)&sKT[k * 64 + tn];
            unsigned long long b01 = pack2(k4.x, k4.y);
            unsigned long long b23 = pack2(k4.z, k4.w);
            unsigned long long aa;
            aa = pack2(q4.x, q4.x); ffma2(acc[0][0], aa, b01); ffma2(acc[0][1], aa, b23);
            aa = pack2(q4.y, q4.y); ffma2(acc[1][0], aa, b01); ffma2(acc[1][1], aa, b23);
            aa = pack2(q4.z, q4.z); ffma2(acc[2][0], aa, b01); ffma2(acc[2][1], aa, b23);
            aa = pack2(q4.w, q4.w); ffma2(acc[3][0], aa, b01); ffma2(acc[3][1], aa, b23);
        }
        const float scale = 0.08838834764831845f;  // 1/sqrt(128)
#pragma unroll
        for (int i = 0; i < 4; i++) {
            float2 p0 = unpack2(acc[i][0]);
            float2 p1 = unpack2(acc[i][1]);
            float4 o = make_float4(p0.x * scale, p0.y * scale, p1.x * scale, p1.y * scale);
            *(float4*)&sS[(tm + i) * 68 + tn] = o;
        }
    }
    __syncthreads();

    // Softmax: warp-parallel per row (causal). Warp w handles rows w, w+8, ...
    for (int t = wid; t < TT; t += 8) {
        float* row = sS + t * 68;
        float e0 = -1e30f, e1 = -1e30f;
        bool v0 = (lane < 25) && (2 * lane <= t);
        bool v1 = (lane < 25) && (2 * lane + 1 <= t);
        float2 v = make_float2(0.f, 0.f);
        if (lane < 25) v = *(float2*)(row + 2 * lane);
        if (v0) e0 = v.x;
        if (v1) e1 = v.y;
        float mx = fmaxf(e0, e1);
#pragma unroll
        for (int o = 16; o; o >>= 1) mx = fmaxf(mx, __shfl_xor_sync(0xFFFFFFFFu, mx, o));
        float x0 = v0 ? expf(e0 - mx) : 0.f;
        float x1 = v1 ? expf(e1 - mx) : 0.f;
        float sum = x0 + x1;
#pragma unroll
        for (int o = 16; o; o >>= 1) sum += __shfl_xor_sync(0xFFFFFFFFu, sum, o);
        float inv = 1.0f / sum;
        if (lane < 25) *(float2*)(row + 2 * lane) = make_float2(x0 * inv, x1 * inv);
    }
    __syncthreads();

    // Phase B: O = P*V
    {
        const int tm = (tid >> 5) * 8;   // t
        const int tn = (tid & 31) * 4;   // d
        unsigned long long acc[8][2];
#pragma unroll
        for (int i = 0; i < 8; i++) { acc[i][0] = 0ull; acc[i][1] = 0ull; }

#pragma unroll 2
        for (int s = 0; s < TT; s++) {
            float4 v4 = *(const float4*)&sV[s * 128 + tn];
            unsigned long long b01 = pack2(v4.x, v4.y);
            unsigned long long b23 = pack2(v4.z, v4.w);
#pragma unroll
            for (int i = 0; i < 8; i++) {
                float p = sS[(tm + i) * 68 + s];
                unsigned long long aa = pack2(p, p);
                ffma2(acc[i][0], aa, b01);
                ffma2(acc[i][1], aa, b23);
            }
        }

        float* Ob = g_O + (long long)(b * TT) * HD + h * DH;
#pragma unroll
        for (int i = 0; i < 8; i++) {
            int t = tm + i;
            if (t < TT) {
                float2 p0 = unpack2(acc[i][0]);
                float2 p1 = unpack2(acc[i][1]);
                float4 o = make_float4(p0.x, p0.y, p1.x, p1.y);
                *(float4*)(Ob + (long long)t * HD + tn) = o;
            }
        }
    }
}

// a-partials: K split 8x128.   grid (50, 8)
__global__ void proj_o_part_kernel(const float* __restrict__ Wo) {
    int m0 = blockIdx.x * 64;
    int ks = blockIdx.y;
    gemm64_core(g_O + (long long)m0 * HD + ks * 128, HD,
                Wo + (long long)ks * 128 * EDIM, EDIM, nullptr,
                g_part + (long long)ks * NTOK * EDIM + (long long)m0 * EDIM, EDIM,
                128, 0);
}
// y-partials: K split 4x64.    grid (50, 4)
__global__ void mlp2_part_kernel(const float* __restrict__ W2) {
    int m0 = blockIdx.x * 64;
    int ks = blockIdx.y;
    gemm64_core(g_m + (long long)m0 * MDIM + ks * 64, MDIM,
                W2 + (long long)ks * 64 * EDIM, EDIM, nullptr,
                g_part + (long long)ks * NTOK * EDIM + (long long)m0 * EDIM, EDIM,
                64, 0);
}
// Deterministic partial reduce + bias into g_a (proj_o path).
template <int NSPLIT>
__global__ void reduce_part_a_kernel(const float* __restrict__ bias) {
    int i = blockIdx.x * 256 + threadIdx.x;
    if (i >= NTOK * EDIM) return;
    float s = bias[i & 63];
#pragma unroll
    for (int k = 0; k < NSPLIT; k++) s += g_part[(long long)k * NTOK * EDIM + i];
    g_a[i] = s;
}

// m = gelu(a @ W1 + b1)       grid (50, 4)
__global__ void mlp1_kernel(const float* __restrict__ W1, const float* __restrict__ b1) {
    int m0 = blockIdx.x * 64;
    int n0 = blockIdx.y * 64;
    gemm64_core(g_a + (long long)m0 * EDIM, EDIM, W1 + n0, MDIM, b1 + n0,
                g_m + (long long)m0 * MDIM + n0, MDIM, EDIM, 1);
}

// ---------------------------------------------------------------------------
// Split-fp16 helpers
// ---------------------------------------------------------------------------
__device__ __forceinline__ void split_fp16(float v, unsigned short& hi, unsigned short& lo) {
    __half h = __float2half(v);
    float r = v - __half2float(h);
    __half l = __float2half(r);
    hi = *reinterpret_cast<unsigned short*>(&h);
    lo = *reinterpret_cast<unsigned short*>(&l);
}

// Fused: y = sum(4 partials)+b2, then split to fp16 hi/lo planes (g_y never
// materialized). One warp per token row; lane handles elements 2l, 2l+1.
// grid NTOK/8 x 256.
__global__ void reduce_split_y_kernel(const float* __restrict__ b2) {
    int r = blockIdx.x * 8 + (threadIdx.x >> 5);
    int lane = threadIdx.x & 31;
    int e = lane * 2;
    float2 s = *(const float2*)(b2 + e);
#pragma unroll
    for (int k = 0; k < 4; k++) {
        float2 p = *(const float2*)(g_part + (long long)k * NTOK * EDIM + r * 64 + e);
        s.x += p.x; s.y += p.y;
    }
    unsigned short h0, l0, h1, l1;
    split_fp16(s.x, h0, l0);
    split_fp16(s.y, h1, l1);
    ((unsigned int*)g_ybf)[r * 64 + lane]      = (unsigned int)h0 | ((unsigned int)h1 << 16);
    ((unsigned int*)g_ybf)[r * 64 + 32 + lane] = (unsigned int)l0 | ((unsigned int)l1 << 16);
}

// B' = [hi(64)] per vocab row (fp16). Wf is [E][V] -> transpose via smem tile.
__global__ void split_wf_kernel(const float* __restrict__ Wf) {
    __shared__ unsigned short sH[128][68];
    int n0 = blockIdx.x * 128;
    int tid = threadIdx.x;  // 128
    for (int i = tid; i < 64 * 128; i += 128) {
        int e = i >> 7;
        int n = i & 127;
        float v = Wf[(long long)e * VOC + n0 + n];
        __half h = __float2half(v);
        sH[n][e] = *reinterpret_cast<unsigned short*>(&h);
    }
    __syncthreads();
    for (int i = tid; i < 128 * 32; i += 128) {
        int n = i >> 5, j = i & 31;
        unsigned int w = (unsigned int)sH[n][2*j] | ((unsigned int)sH[n][2*j+1] << 16);
        ((unsigned int*)g_Wfb)[(long long)(n0 + n) * 32 + j] = w;
    }
}

// ---------------------------------------------------------------------------
// Final vocab GEMM on mma.sync m16n8k16 fp16, direct-lds fragments.
// Block tile 128x128, 8 warps (4m x 2n), warp tile 32x64.
// K=128 as 2 A-chunks (hi, lo) x K=64; B (hi) loaded ONCE, reused by both.
// Smem: 512 + 2 * 128 * 72 * 2B = 37376 B < 48KB default.
// ---------------------------------------------------------------------------
#define FC_LDS   72                         // 64 + 8 pad fp16 per smem row

__global__ __launch_bounds__(256) void final_mma_kernel(
        const float* __restrict__ bf, float* __restrict__ out) {
    __shared__ float sBias[128];
    __shared__ __align__(16) __half sA[128 * FC_LDS];
    __shared__ __align__(16) __half sB[128 * FC_LDS];

    const int tid = threadIdx.x;
    const int m0 = blockIdx.x * 128;
    const int n0 = blockIdx.y * 128;

    if (tid < 128) sBias[tid] = bf[n0 + tid];

    const uint4* __restrict__ Ag = g_ybf + (long long)m0 * 16;
    const uint4* __restrict__ Bg = g_Wfb + (long long)n0 * 8;

    const int wid  = tid >> 5, lane = tid & 31;
    const int wm   = wid >> 1;            // 0..3  (m strip of 32)
    const int wn   = wid & 1;             // 0..1  (n strip of 64)
    const int l4   = lane >> 2;           // 0..7  groupID
    const int lm   = lane & 3;            // 0..3  threadID_in_group

    // Load B (once) and A chunk 0 (hi plane).
#pragma unroll
    for (int i = 0; i < 4; i++) {
        int idx = i * 256 + tid;          // 0..1023
        int r = idx >> 3, q = idx & 7;
        *(uint4*)(sB + r * FC_LDS + q * 8) = Bg[(long long)r * 8 + q];
        *(uint4*)(sA + r * FC_LDS + q * 8) = Ag[(long long)r * 16 + q];
    }
    __syncthreads();

    float acc[2][8][4];
#pragma unroll
    for (int mf = 0; mf < 2; mf++)
#pragma unroll
        for (int nf = 0; nf < 8; nf++)
#pragma unroll
            for (int c = 0; c < 4; c++) acc[mf][nf][c] = 0.0f;

#pragma unroll
    for (int ch = 0; ch < 2; ch++) {
#pragma unroll
        for (int ks = 0; ks < 4; ks++) {
            const int k0 = ks * 16;
            uint32_t a[2][4];
#pragma unroll
            for (int mf = 0; mf < 2; mf++) {
                const __half* base = sA + (wm * 32 + mf * 16 + l4) * FC_LDS + k0 + lm * 2;
                a[mf][0] = *(const uint32_t*)(base);
                a[mf][1] = *(const uint32_t*)(base + 8 * FC_LDS);
                a[mf][2] = *(const uint32_t*)(base + 8);
                a[mf][3] = *(const uint32_t*)(base + 8 * FC_LDS + 8);
            }
            uint32_t b[8][2];
#pragma unroll
            for (int nf = 0; nf < 8; nf++) {
                const __half* base = sB + (wn * 64 + nf * 8 + l4) * FC_LDS + k0 + lm * 2;
                b[nf][0] = *(const uint32_t*)(base);
                b[nf][1] = *(const uint32_t*)(base + 8);
            }
#pragma unroll
            for (int mf = 0; mf < 2; mf++)
#pragma unroll
                for (int nf = 0; nf < 8; nf++)
                    mma16816(acc[mf][nf], a[mf], b[nf]);
        }
        if (ch == 0) {
            // Swap in A chunk 1 (lo plane); B stays resident.
            __syncthreads();
#pragma unroll
            for (int i = 0; i < 4; i++) {
                int idx = i * 256 + tid;
                int r = idx >> 3, q = idx & 7;
                *(uint4*)(sA + r * FC_LDS + q * 8) = Ag[(long long)r * 16 + 8 + q];
            }
            __syncthreads();
        }
    }

    // Epilogue: add bias, store fp32.
#pragma unroll
    for (int mf = 0; mf < 2; mf++) {
        int row = m0 + wm * 32 + mf * 16 + l4;
        float* o0 = out + (long long)row * VOC + n0;
        float* o1 = out + (long long)(row + 8) * VOC + n0;
#pragma unroll
        for (int nf = 0; nf < 8; nf++) {
            int colr = wn * 64 + nf * 8 + lm * 2;
            float bx = sBias[colr], by = sBias[colr + 1];
            float2 v0 = make_float2(acc[mf][nf][0] + bx, acc[mf][nf][1] + by);
            float2 v1 = make_float2(acc[mf][nf][2] + bx, acc[mf][nf][3] + by);
            *(float2*)(o0 + colr) = v0;
            *(float2*)(o1 + colr) = v1;
        }
    }
}

// ---------------------------------------------------------------------------
extern "C" void kernel_launch(void* const* d_in, const int* in_sizes, int n_in,
                              void* d_out, int out_size) {
    (void)in_sizes; (void)n_in; (void)out_size;
    const int*   x   = (const int*)  d_in[0];
    const float* tok = (const float*)d_in[1];
    const float* pos = (const float*)d_in[2];
    const float* Wq  = (const float*)d_in[3];
    const float* bq  = (const float*)d_in[4];
    const float* Wk  = (const float*)d_in[5];
    const float* bk  = (const float*)d_in[6];
    const float* Wv  = (const float*)d_in[7];
    const float* bv  = (const float*)d_in[8];
    const float* Wo  = (const float*)d_in[9];
    const float* bo  = (const float*)d_in[10];
    const float* W1  = (const float*)d_in[11];
    const float* b1  = (const float*)d_in[12];
    const float* W2  = (const float*)d_in[13];
    const float* b2  = (const float*)d_in[14];
    const float* Wf  = (const float*)d_in[15];
    const float* bf  = (const float*)d_in[16];
    float* out = (float*)d_out;

    cudaFuncSetAttribute(attn_kernel, cudaFuncAttributeMaxDynamicSharedMemorySize, AT_SMEM);

    // Wf split is independent of everything else — kick it off first.
    split_wf_kernel<<<VOC / 128, 128>>>(Wf);

    qkv_embed_kernel<<<dim3(NTOK / 64, 2 * NH, 3), 256>>>(x, tok, pos,
                                                          Wq, bq, Wk, bk, Wv, bv);
    attn_kernel<<<BATCH * NH, 256, AT_SMEM>>>();

    proj_o_part_kernel<<<dim3(NTOK / 64, 8), 256>>>(Wo);
    reduce_part_a_kernel<8><<<(NTOK * EDIM + 255) / 256, 256>>>(bo);

    mlp1_kernel<<<dim3(NTOK / 64, MDIM / 64), 256>>>(W1, b1);

    mlp2_part_kernel<<<dim3(NTOK / 64, 4), 256>>>(W2);
    reduce_split_y_kernel<<<NTOK / 8, 256>>>(b2);

    final_mma_kernel<<<dim3(NTOK / 128, VOC / 128), 256>>>(bf, out);
}